// round 1
// baseline (speedup 1.0000x reference)
#include <cuda_runtime.h>

#define BATCH 16
#define SEQ   4096
#define CH    512
#define DIM   64

// Scratch (allocation-free per harness rules)
__device__ float g_q[BATCH * SEQ * DIM];
__device__ float g_k[BATCH * SEQ * DIM];
__device__ float g_v[BATCH * SEQ * CH];

// ---------------------------------------------------------------------------
// proj: C[M,N] = A[M,512] @ W[512,N] + bias   (A=x row-major, W (in,out) row-major)
// Tile 128x64x32, 256 threads, 8x4 per thread.
// ---------------------------------------------------------------------------
__global__ __launch_bounds__(256, 2)
void proj_kernel(const float* __restrict__ A, const float* __restrict__ W,
                 const float* __restrict__ bias, float* __restrict__ C, int N) {
    const int K = CH;  // 512
    __shared__ float As[32][132];
    __shared__ float Ws[32][64];
    const int bm = blockIdx.y * 128;
    const int bn = blockIdx.x * 64;
    const int tid = threadIdx.x;
    const int tn = tid & 15;
    const int tm = tid >> 4;
    float acc[8][4] = {};

    for (int k0 = 0; k0 < K; k0 += 32) {
        #pragma unroll
        for (int i = 0; i < 4; i++) {
            int fidx = tid + i * 256;        // 0..1023
            int row  = fidx >> 3;            // 0..127
            int kc   = (fidx & 7) * 4;       // 0..28
            float4 t = *(const float4*)(A + (size_t)(bm + row) * K + k0 + kc);
            As[kc + 0][row] = t.x; As[kc + 1][row] = t.y;
            As[kc + 2][row] = t.z; As[kc + 3][row] = t.w;
        }
        #pragma unroll
        for (int i = 0; i < 2; i++) {
            int fidx = tid + i * 256;        // 0..511
            int kr   = fidx >> 4;            // 0..31
            int nc   = (fidx & 15) * 4;      // 0..60
            *(float4*)&Ws[kr][nc] = *(const float4*)(W + (size_t)(k0 + kr) * N + bn + nc);
        }
        __syncthreads();
        #pragma unroll
        for (int kk = 0; kk < 32; kk++) {
            float4 a0 = *(const float4*)&As[kk][tm * 8];
            float4 a1 = *(const float4*)&As[kk][tm * 8 + 4];
            float4 w0 = *(const float4*)&Ws[kk][tn * 4];
            float a[8] = {a0.x, a0.y, a0.z, a0.w, a1.x, a1.y, a1.z, a1.w};
            float w[4] = {w0.x, w0.y, w0.z, w0.w};
            #pragma unroll
            for (int i = 0; i < 8; i++)
                #pragma unroll
                for (int j = 0; j < 4; j++)
                    acc[i][j] = fmaf(a[i], w[j], acc[i][j]);
        }
        __syncthreads();
    }
    #pragma unroll
    for (int i = 0; i < 8; i++) {
        size_t row = bm + tm * 8 + i;
        int col = bn + tn * 4;
        float4 o;
        o.x = acc[i][0] + bias[col + 0];
        o.y = acc[i][1] + bias[col + 1];
        o.z = acc[i][2] + bias[col + 2];
        o.w = acc[i][3] + bias[col + 3];
        *(float4*)(C + row * N + col) = o;
    }
}

// ---------------------------------------------------------------------------
// energy: E[b, m, n] = sum_d Q[b,m,d] * K[b,n,d]   (logits, unnormalized)
// Tile 128x128, D=64 in two 32-chunks, 256 threads, 8x8 per thread.
// ---------------------------------------------------------------------------
__global__ __launch_bounds__(256, 2)
void energy_kernel(const float* __restrict__ Q, const float* __restrict__ Kd,
                   float* __restrict__ E) {
    __shared__ float Qs[32][132];
    __shared__ float Ks[32][132];
    const int b  = blockIdx.z;
    const int bm = blockIdx.y * 128;   // query rows
    const int bn = blockIdx.x * 128;   // key rows
    const float* Qb = Q  + (size_t)b * SEQ * DIM;
    const float* Kb = Kd + (size_t)b * SEQ * DIM;
    float* Eb = E + (size_t)b * SEQ * SEQ;
    const int tid = threadIdx.x;
    const int tn = tid & 15;
    const int tm = tid >> 4;
    float acc[8][8] = {};

    for (int k0 = 0; k0 < DIM; k0 += 32) {
        #pragma unroll
        for (int i = 0; i < 4; i++) {
            int fidx = tid + i * 256;
            int row  = fidx >> 3;
            int kc   = (fidx & 7) * 4;
            float4 t = *(const float4*)(Qb + (size_t)(bm + row) * DIM + k0 + kc);
            Qs[kc + 0][row] = t.x; Qs[kc + 1][row] = t.y;
            Qs[kc + 2][row] = t.z; Qs[kc + 3][row] = t.w;
            float4 u = *(const float4*)(Kb + (size_t)(bn + row) * DIM + k0 + kc);
            Ks[kc + 0][row] = u.x; Ks[kc + 1][row] = u.y;
            Ks[kc + 2][row] = u.z; Ks[kc + 3][row] = u.w;
        }
        __syncthreads();
        #pragma unroll
        for (int kk = 0; kk < 32; kk++) {
            float4 a0 = *(const float4*)&Qs[kk][tm * 8];
            float4 a1 = *(const float4*)&Qs[kk][tm * 8 + 4];
            float4 b0 = *(const float4*)&Ks[kk][tn * 8];
            float4 b1 = *(const float4*)&Ks[kk][tn * 8 + 4];
            float a[8] = {a0.x, a0.y, a0.z, a0.w, a1.x, a1.y, a1.z, a1.w};
            float w[8] = {b0.x, b0.y, b0.z, b0.w, b1.x, b1.y, b1.z, b1.w};
            #pragma unroll
            for (int i = 0; i < 8; i++)
                #pragma unroll
                for (int j = 0; j < 8; j++)
                    acc[i][j] = fmaf(a[i], w[j], acc[i][j]);
        }
        __syncthreads();
    }
    #pragma unroll
    for (int i = 0; i < 8; i++) {
        size_t row = bm + tm * 8 + i;
        int col = bn + tn * 8;
        float4 o0 = {acc[i][0], acc[i][1], acc[i][2], acc[i][3]};
        float4 o1 = {acc[i][4], acc[i][5], acc[i][6], acc[i][7]};
        *(float4*)(Eb + row * SEQ + col)     = o0;
        *(float4*)(Eb + row * SEQ + col + 4) = o1;
    }
}

// ---------------------------------------------------------------------------
// softmax: in-place row softmax over 4096 keys. One block (256 thr) per row;
// row lives entirely in registers (16 floats/thread).
// ---------------------------------------------------------------------------
__global__ __launch_bounds__(256)
void softmax_kernel(float* __restrict__ E) {
    const int tid = threadIdx.x;
    float4* p = (float4*)(E + (size_t)blockIdx.x * SEQ);
    float4 v[4];
    float mx = -3.4e38f;
    #pragma unroll
    for (int i = 0; i < 4; i++) {
        v[i] = p[tid + i * 256];
        mx = fmaxf(mx, fmaxf(fmaxf(v[i].x, v[i].y), fmaxf(v[i].z, v[i].w)));
    }
    __shared__ float sred[8];
    #pragma unroll
    for (int o = 16; o > 0; o >>= 1) mx = fmaxf(mx, __shfl_xor_sync(0xffffffffu, mx, o));
    if ((tid & 31) == 0) sred[tid >> 5] = mx;
    __syncthreads();
    if (tid == 0) {
        float m = sred[0];
        #pragma unroll
        for (int i = 1; i < 8; i++) m = fmaxf(m, sred[i]);
        sred[0] = m;
    }
    __syncthreads();
    mx = sred[0];
    __syncthreads();

    float s = 0.f;
    #pragma unroll
    for (int i = 0; i < 4; i++) {
        v[i].x = __expf(v[i].x - mx);
        v[i].y = __expf(v[i].y - mx);
        v[i].z = __expf(v[i].z - mx);
        v[i].w = __expf(v[i].w - mx);
        s += (v[i].x + v[i].y) + (v[i].z + v[i].w);
    }
    #pragma unroll
    for (int o = 16; o > 0; o >>= 1) s += __shfl_xor_sync(0xffffffffu, s, o);
    if ((tid & 31) == 0) sred[tid >> 5] = s;
    __syncthreads();
    if (tid == 0) {
        float t = 0.f;
        #pragma unroll
        for (int i = 0; i < 8; i++) t += sred[i];
        sred[0] = t;
    }
    __syncthreads();
    float inv = 1.0f / sred[0];
    #pragma unroll
    for (int i = 0; i < 4; i++) {
        v[i].x *= inv; v[i].y *= inv; v[i].z *= inv; v[i].w *= inv;
        p[tid + i * 256] = v[i];
    }
}

// ---------------------------------------------------------------------------
// av: Out[b,m,c] = gamma * sum_k Att[b,m,k] * V[b,k,c] + X[b,m,c]
// Tile 128x128x32, 256 threads, 8x8 per thread.
// ---------------------------------------------------------------------------
__global__ __launch_bounds__(256, 2)
void av_kernel(const float* __restrict__ Att, const float* __restrict__ V,
               const float* __restrict__ X, const float* __restrict__ gamma,
               float* __restrict__ Out) {
    __shared__ float As[32][132];
    __shared__ float Vs[32][128];
    const int b  = blockIdx.z;
    const int bm = blockIdx.y * 128;   // query rows
    const int bn = blockIdx.x * 128;   // channel cols
    const float* Ab = Att + (size_t)b * SEQ * SEQ;
    const float* Vb = V   + (size_t)b * SEQ * CH;
    const float* Xb = X   + (size_t)b * SEQ * CH;
    float* Ob = Out + (size_t)b * SEQ * CH;
    const int tid = threadIdx.x;
    const int tn = tid & 15;
    const int tm = tid >> 4;
    float acc[8][8] = {};

    for (int k0 = 0; k0 < SEQ; k0 += 32) {
        #pragma unroll
        for (int i = 0; i < 4; i++) {
            int fidx = tid + i * 256;        // 0..1023
            int row  = fidx >> 3;            // 0..127
            int kc   = (fidx & 7) * 4;       // 0..28
            float4 t = *(const float4*)(Ab + (size_t)(bm + row) * SEQ + k0 + kc);
            As[kc + 0][row] = t.x; As[kc + 1][row] = t.y;
            As[kc + 2][row] = t.z; As[kc + 3][row] = t.w;
            int vr = fidx >> 5;              // 0..31
            int vc = (fidx & 31) * 4;        // 0..124
            *(float4*)&Vs[vr][vc] = *(const float4*)(Vb + (size_t)(k0 + vr) * CH + bn + vc);
        }
        __syncthreads();
        #pragma unroll
        for (int kk = 0; kk < 32; kk++) {
            float4 a0 = *(const float4*)&As[kk][tm * 8];
            float4 a1 = *(const float4*)&As[kk][tm * 8 + 4];
            float4 b0 = *(const float4*)&Vs[kk][tn * 8];
            float4 b1 = *(const float4*)&Vs[kk][tn * 8 + 4];
            float a[8] = {a0.x, a0.y, a0.z, a0.w, a1.x, a1.y, a1.z, a1.w};
            float w[8] = {b0.x, b0.y, b0.z, b0.w, b1.x, b1.y, b1.z, b1.w};
            #pragma unroll
            for (int i = 0; i < 8; i++)
                #pragma unroll
                for (int j = 0; j < 8; j++)
                    acc[i][j] = fmaf(a[i], w[j], acc[i][j]);
        }
        __syncthreads();
    }
    const float g = gamma[0];
    #pragma unroll
    for (int i = 0; i < 8; i++) {
        size_t row = bm + tm * 8 + i;
        int col = bn + tn * 8;
        float4 x0 = *(const float4*)(Xb + row * CH + col);
        float4 x1 = *(const float4*)(Xb + row * CH + col + 4);
        float4 o0, o1;
        o0.x = fmaf(g, acc[i][0], x0.x); o0.y = fmaf(g, acc[i][1], x0.y);
        o0.z = fmaf(g, acc[i][2], x0.z); o0.w = fmaf(g, acc[i][3], x0.w);
        o1.x = fmaf(g, acc[i][4], x1.x); o1.y = fmaf(g, acc[i][5], x1.y);
        o1.z = fmaf(g, acc[i][6], x1.z); o1.w = fmaf(g, acc[i][7], x1.w);
        *(float4*)(Ob + row * CH + col)     = o0;
        *(float4*)(Ob + row * CH + col + 4) = o1;
    }
}

// ---------------------------------------------------------------------------
extern "C" void kernel_launch(void* const* d_in, const int* in_sizes, int n_in,
                              void* d_out, int out_size) {
    const float* x     = (const float*)d_in[0];
    const float* Wq    = (const float*)d_in[1];
    const float* bq    = (const float*)d_in[2];
    const float* Wk    = (const float*)d_in[3];
    const float* bk    = (const float*)d_in[4];
    const float* Wv    = (const float*)d_in[5];
    const float* bv    = (const float*)d_in[6];
    const float* gamma = (const float*)d_in[7];

    float* out = (float*)d_out;                              // [B, N, C]
    float* att = out + (size_t)BATCH * SEQ * CH;             // [B, N, N]

    float *q, *k, *v;
    cudaGetSymbolAddress((void**)&q, g_q);
    cudaGetSymbolAddress((void**)&k, g_k);
    cudaGetSymbolAddress((void**)&v, g_v);

    const int M = BATCH * SEQ;  // 65536

    // Projections
    proj_kernel<<<dim3(DIM / 64, M / 128), 256>>>(x, Wq, bq, q, DIM);
    proj_kernel<<<dim3(DIM / 64, M / 128), 256>>>(x, Wk, bk, k, DIM);
    proj_kernel<<<dim3(CH  / 64, M / 128), 256>>>(x, Wv, bv, v, CH);

    // Logits straight into attention output region
    energy_kernel<<<dim3(SEQ / 128, SEQ / 128, BATCH), 256>>>(q, k, att);

    // In-place row softmax
    softmax_kernel<<<M, 256>>>(att);

    // attn @ V, fused gamma-residual epilogue
    av_kernel<<<dim3(CH / 128, SEQ / 128, BATCH), 256>>>(att, v, x, gamma, out);
}

// round 4
// speedup vs baseline: 2.0203x; 2.0203x over previous
#include <cuda_runtime.h>
#include <cstdint>

#define BATCH 16
#define SEQ   4096
#define CH    512
#define DIM   64

// Scratch (allocation-free per harness rules)
__device__ float g_q[BATCH * SEQ * DIM];
__device__ float g_k[BATCH * SEQ * DIM];
__device__ float g_v[BATCH * SEQ * CH];

// ===========================================================================
// helpers
// ===========================================================================
__device__ __forceinline__ uint32_t smem_u32(const void* p) {
    uint32_t a;
    asm("{ .reg .u64 t; cvta.to.shared.u64 t, %1; cvt.u32.u64 %0, t; }" : "=r"(a) : "l"(p));
    return a;
}
__device__ __forceinline__ float tf32r(float x) {
    uint32_t r;
    asm("cvt.rna.tf32.f32 %0, %1;" : "=r"(r) : "f"(x));
    return __uint_as_float(r);
}
__device__ __forceinline__ void cp16(uint32_t dst, const void* src) {
    asm volatile("cp.async.cg.shared.global [%0], [%1], 16;" :: "r"(dst), "l"(src));
}
#define CP_COMMIT() asm volatile("cp.async.commit_group;" ::: "memory")
#define CP_WAIT_1() asm volatile("cp.async.wait_group 1;" ::: "memory")
#define CP_WAIT_0() asm volatile("cp.async.wait_group 0;" ::: "memory")

// ===========================================================================
// proj: C[M,N] = A[M,512] @ W[512,N] + bias.  round_out: store tf32-rounded.
// ===========================================================================
__global__ __launch_bounds__(256, 2)
void proj_kernel(const float* __restrict__ A, const float* __restrict__ W,
                 const float* __restrict__ bias, float* __restrict__ C, int N,
                 int round_out) {
    const int K = CH;
    __shared__ float As[32][132];
    __shared__ float Ws[32][64];
    const int bm = blockIdx.y * 128;
    const int bn = blockIdx.x * 64;
    const int tid = threadIdx.x;
    const int tn = tid & 15;
    const int tm = tid >> 4;
    float acc[8][4] = {};

    for (int k0 = 0; k0 < K; k0 += 32) {
        #pragma unroll
        for (int i = 0; i < 4; i++) {
            int fidx = tid + i * 256;
            int row  = fidx >> 3;
            int kc   = (fidx & 7) * 4;
            float4 t = *(const float4*)(A + (size_t)(bm + row) * K + k0 + kc);
            As[kc + 0][row] = t.x; As[kc + 1][row] = t.y;
            As[kc + 2][row] = t.z; As[kc + 3][row] = t.w;
        }
        #pragma unroll
        for (int i = 0; i < 2; i++) {
            int fidx = tid + i * 256;
            int kr   = fidx >> 4;
            int nc   = (fidx & 15) * 4;
            *(float4*)&Ws[kr][nc] = *(const float4*)(W + (size_t)(k0 + kr) * N + bn + nc);
        }
        __syncthreads();
        #pragma unroll
        for (int kk = 0; kk < 32; kk++) {
            float4 a0 = *(const float4*)&As[kk][tm * 8];
            float4 a1 = *(const float4*)&As[kk][tm * 8 + 4];
            float4 w0 = *(const float4*)&Ws[kk][tn * 4];
            float a[8] = {a0.x, a0.y, a0.z, a0.w, a1.x, a1.y, a1.z, a1.w};
            float w[4] = {w0.x, w0.y, w0.z, w0.w};
            #pragma unroll
            for (int i = 0; i < 8; i++)
                #pragma unroll
                for (int j = 0; j < 4; j++)
                    acc[i][j] = fmaf(a[i], w[j], acc[i][j]);
        }
        __syncthreads();
    }
    #pragma unroll
    for (int i = 0; i < 8; i++) {
        size_t row = bm + tm * 8 + i;
        int col = bn + tn * 4;
        float4 o;
        o.x = acc[i][0] + bias[col + 0];
        o.y = acc[i][1] + bias[col + 1];
        o.z = acc[i][2] + bias[col + 2];
        o.w = acc[i][3] + bias[col + 3];
        if (round_out) {
            o.x = tf32r(o.x); o.y = tf32r(o.y);
            o.z = tf32r(o.z); o.w = tf32r(o.w);
        }
        *(float4*)(C + row * N + col) = o;
    }
}

// ===========================================================================
// energy: E[b,m,n] = sum_d Q[b,m,d] * K[b,n,d]   (fp32 SIMT)
// ===========================================================================
__global__ __launch_bounds__(256, 2)
void energy_kernel(const float* __restrict__ Q, const float* __restrict__ Kd,
                   float* __restrict__ E) {
    __shared__ float Qs[32][132];
    __shared__ float Ks[32][132];
    const int b  = blockIdx.z;
    const int bm = blockIdx.y * 128;
    const int bn = blockIdx.x * 128;
    const float* Qb = Q  + (size_t)b * SEQ * DIM;
    const float* Kb = Kd + (size_t)b * SEQ * DIM;
    float* Eb = E + (size_t)b * SEQ * SEQ;
    const int tid = threadIdx.x;
    const int tn = tid & 15;
    const int tm = tid >> 4;
    float acc[8][8] = {};

    for (int k0 = 0; k0 < DIM; k0 += 32) {
        #pragma unroll
        for (int i = 0; i < 4; i++) {
            int fidx = tid + i * 256;
            int row  = fidx >> 3;
            int kc   = (fidx & 7) * 4;
            float4 t = *(const float4*)(Qb + (size_t)(bm + row) * DIM + k0 + kc);
            Qs[kc + 0][row] = t.x; Qs[kc + 1][row] = t.y;
            Qs[kc + 2][row] = t.z; Qs[kc + 3][row] = t.w;
            float4 u = *(const float4*)(Kb + (size_t)(bn + row) * DIM + k0 + kc);
            Ks[kc + 0][row] = u.x; Ks[kc + 1][row] = u.y;
            Ks[kc + 2][row] = u.z; Ks[kc + 3][row] = u.w;
        }
        __syncthreads();
        #pragma unroll
        for (int kk = 0; kk < 32; kk++) {
            float4 a0 = *(const float4*)&Qs[kk][tm * 8];
            float4 a1 = *(const float4*)&Qs[kk][tm * 8 + 4];
            float4 b0 = *(const float4*)&Ks[kk][tn * 8];
            float4 b1 = *(const float4*)&Ks[kk][tn * 8 + 4];
            float a[8] = {a0.x, a0.y, a0.z, a0.w, a1.x, a1.y, a1.z, a1.w};
            float w[8] = {b0.x, b0.y, b0.z, b0.w, b1.x, b1.y, b1.z, b1.w};
            #pragma unroll
            for (int i = 0; i < 8; i++)
                #pragma unroll
                for (int j = 0; j < 8; j++)
                    acc[i][j] = fmaf(a[i], w[j], acc[i][j]);
        }
        __syncthreads();
    }
    #pragma unroll
    for (int i = 0; i < 8; i++) {
        size_t row = bm + tm * 8 + i;
        int col = bn + tn * 8;
        float4 o0 = {acc[i][0], acc[i][1], acc[i][2], acc[i][3]};
        float4 o1 = {acc[i][4], acc[i][5], acc[i][6], acc[i][7]};
        *(float4*)(Eb + row * SEQ + col)     = o0;
        *(float4*)(Eb + row * SEQ + col + 4) = o1;
    }
}

// ===========================================================================
// softmax: in-place row softmax; final probs stored tf32-rounded.
// ===========================================================================
__global__ __launch_bounds__(256)
void softmax_kernel(float* __restrict__ E) {
    const int tid = threadIdx.x;
    float4* p = (float4*)(E + (size_t)blockIdx.x * SEQ);
    float4 v[4];
    float mx = -3.4e38f;
    #pragma unroll
    for (int i = 0; i < 4; i++) {
        v[i] = p[tid + i * 256];
        mx = fmaxf(mx, fmaxf(fmaxf(v[i].x, v[i].y), fmaxf(v[i].z, v[i].w)));
    }
    __shared__ float sred[8];
    #pragma unroll
    for (int o = 16; o > 0; o >>= 1) mx = fmaxf(mx, __shfl_xor_sync(0xffffffffu, mx, o));
    if ((tid & 31) == 0) sred[tid >> 5] = mx;
    __syncthreads();
    if (tid == 0) {
        float m = sred[0];
        #pragma unroll
        for (int i = 1; i < 8; i++) m = fmaxf(m, sred[i]);
        sred[0] = m;
    }
    __syncthreads();
    mx = sred[0];
    __syncthreads();

    float s = 0.f;
    #pragma unroll
    for (int i = 0; i < 4; i++) {
        v[i].x = __expf(v[i].x - mx);
        v[i].y = __expf(v[i].y - mx);
        v[i].z = __expf(v[i].z - mx);
        v[i].w = __expf(v[i].w - mx);
        s += (v[i].x + v[i].y) + (v[i].z + v[i].w);
    }
    #pragma unroll
    for (int o = 16; o > 0; o >>= 1) s += __shfl_xor_sync(0xffffffffu, s, o);
    if ((tid & 31) == 0) sred[tid >> 5] = s;
    __syncthreads();
    if (tid == 0) {
        float t = 0.f;
        #pragma unroll
        for (int i = 0; i < 8; i++) t += sred[i];
        sred[0] = t;
    }
    __syncthreads();
    float inv = 1.0f / sred[0];
    #pragma unroll
    for (int i = 0; i < 4; i++) {
        v[i].x = tf32r(v[i].x * inv);
        v[i].y = tf32r(v[i].y * inv);
        v[i].z = tf32r(v[i].z * inv);
        v[i].w = tf32r(v[i].w * inv);
        p[tid + i * 256] = v[i];
    }
}

// ===========================================================================
// av_mma: Out[b,m,c] = gamma * (Att @ V)[b,m,c] + X[b,m,c]
// Legacy tensor path: mma.sync m16n8k8 tf32. Block 128x128xK32, 8 warps of
// 64x32, 2-stage cp.async double buffer.
// Smem (floats): A stage 128x36, B stage 32x136.
// ===========================================================================
#define A_STRIDE 36
#define B_STRIDE 136
#define A_STAGE_F (128 * A_STRIDE)      // 4608 floats
#define B_STAGE_F (32 * B_STRIDE)       // 4352 floats
#define AV_SMEM_F (2 * A_STAGE_F + 2 * B_STAGE_F)   // 17920 floats = 71680 B
#define AV_SMEM_BYTES (AV_SMEM_F * 4)

__device__ __forceinline__ void av_load_stage(uint32_t sb, const float* __restrict__ Ab,
                                              const float* __restrict__ Vb,
                                              int k0, int buf, int tid, int bn) {
    uint32_t abase = sb + buf * (A_STAGE_F * 4);
    #pragma unroll
    for (int j = 0; j < 4; j++) {
        int idx = tid + j * 256;         // 0..1023
        int r   = idx >> 3;              // 0..127
        int c   = idx & 7;               // 16B chunk
        cp16(abase + (r * A_STRIDE + c * 4) * 4, Ab + (size_t)r * SEQ + k0 + c * 4);
    }
    uint32_t bbase = sb + (2 * A_STAGE_F + buf * B_STAGE_F) * 4;
    #pragma unroll
    for (int j = 0; j < 4; j++) {
        int idx = tid + j * 256;         // 0..1023
        int kr  = idx >> 5;              // 0..31
        int c   = idx & 31;              // 16B chunk
        cp16(bbase + (kr * B_STRIDE + c * 4) * 4, Vb + (size_t)(k0 + kr) * CH + bn + c * 4);
    }
}

__global__ __launch_bounds__(256, 2)
void av_mma_kernel(const float* __restrict__ Att, const float* __restrict__ V,
                   const float* __restrict__ X, const float* __restrict__ gamma,
                   float* __restrict__ Out) {
    extern __shared__ float smemf[];
    uint32_t sb = smem_u32(smemf);
    const int tid  = threadIdx.x;
    const int wid  = tid >> 5;
    const int lane = tid & 31;
    const int gid  = lane >> 2;      // 0..7
    const int tig  = lane & 3;       // 0..3
    const int wm   = (wid >> 2) * 64;    // warp m offset: 0 or 64
    const int wn   = (wid & 3) * 32;     // warp n offset: 0,32,64,96

    const int bz = blockIdx.z;
    const int bm = blockIdx.y * 128;
    const int bn = blockIdx.x * 128;
    const float* Ab = Att + ((size_t)bz * SEQ + bm) * SEQ;
    const float* Vb = V   + (size_t)bz * SEQ * CH;

    float acc[16][4];
    #pragma unroll
    for (int i = 0; i < 16; i++)
        #pragma unroll
        for (int j = 0; j < 4; j++) acc[i][j] = 0.f;

    av_load_stage(sb, Ab, Vb, 0,  0, tid, bn); CP_COMMIT();
    av_load_stage(sb, Ab, Vb, 32, 1, tid, bn); CP_COMMIT();

    const int NS = SEQ / 32;   // 128
    for (int s = 0; s < NS; s++) {
        const int buf = s & 1;
        if (s < NS - 1) { CP_WAIT_1(); } else { CP_WAIT_0(); }
        __syncthreads();

        const float* As = smemf + buf * A_STAGE_F;
        const float* Bs = smemf + 2 * A_STAGE_F + buf * B_STAGE_F;

        #pragma unroll
        for (int kk = 0; kk < 32; kk += 8) {
            uint32_t a[4][4], b[4][2];
            #pragma unroll
            for (int mt = 0; mt < 4; mt++) {
                int r = wm + mt * 16 + gid;
                a[mt][0] = __float_as_uint(As[r * A_STRIDE + kk + tig]);
                a[mt][1] = __float_as_uint(As[(r + 8) * A_STRIDE + kk + tig]);
                a[mt][2] = __float_as_uint(As[r * A_STRIDE + kk + tig + 4]);
                a[mt][3] = __float_as_uint(As[(r + 8) * A_STRIDE + kk + tig + 4]);
            }
            #pragma unroll
            for (int nt = 0; nt < 4; nt++) {
                int n = wn + nt * 8 + gid;
                b[nt][0] = __float_as_uint(Bs[(kk + tig) * B_STRIDE + n]);
                b[nt][1] = __float_as_uint(Bs[(kk + tig + 4) * B_STRIDE + n]);
            }
            #pragma unroll
            for (int mt = 0; mt < 4; mt++)
                #pragma unroll
                for (int nt = 0; nt < 4; nt++) {
                    float* c = acc[mt * 4 + nt];
                    asm volatile(
                        "mma.sync.aligned.m16n8k8.row.col.f32.tf32.tf32.f32 "
                        "{%0,%1,%2,%3}, {%4,%5,%6,%7}, {%8,%9}, {%0,%1,%2,%3};"
                        : "+f"(c[0]), "+f"(c[1]), "+f"(c[2]), "+f"(c[3])
                        : "r"(a[mt][0]), "r"(a[mt][1]), "r"(a[mt][2]), "r"(a[mt][3]),
                          "r"(b[nt][0]), "r"(b[nt][1]));
                }
        }
        __syncthreads();
        if (s + 2 < NS) {
            av_load_stage(sb, Ab, Vb, (s + 2) * 32, buf, tid, bn);
            CP_COMMIT();
        }
    }

    // epilogue: fused gamma-residual
    const float g = gamma[0];
    #pragma unroll
    for (int mt = 0; mt < 4; mt++) {
        int r0 = bm + wm + mt * 16 + gid;
        size_t base0 = ((size_t)bz * SEQ + r0) * CH;
        size_t base1 = base0 + 8 * CH;
        #pragma unroll
        for (int nt = 0; nt < 4; nt++) {
            float* c = acc[mt * 4 + nt];
            int col = bn + wn + nt * 8 + 2 * tig;
            float2 x0 = *(const float2*)(X + base0 + col);
            float2 x1 = *(const float2*)(X + base1 + col);
            float2 o0, o1;
            o0.x = fmaf(g, c[0], x0.x); o0.y = fmaf(g, c[1], x0.y);
            o1.x = fmaf(g, c[2], x1.x); o1.y = fmaf(g, c[3], x1.y);
            *(float2*)(Out + base0 + col) = o0;
            *(float2*)(Out + base1 + col) = o1;
        }
    }
}

// ===========================================================================
extern "C" void kernel_launch(void* const* d_in, const int* in_sizes, int n_in,
                              void* d_out, int out_size) {
    const float* x     = (const float*)d_in[0];
    const float* Wq    = (const float*)d_in[1];
    const float* bq    = (const float*)d_in[2];
    const float* Wk    = (const float*)d_in[3];
    const float* bk    = (const float*)d_in[4];
    const float* Wv    = (const float*)d_in[5];
    const float* bv    = (const float*)d_in[6];
    const float* gamma = (const float*)d_in[7];

    float* out = (float*)d_out;                              // [B, N, C]
    float* att = out + (size_t)BATCH * SEQ * CH;             // [B, N, N]

    float *q, *k, *v;
    cudaGetSymbolAddress((void**)&q, g_q);
    cudaGetSymbolAddress((void**)&k, g_k);
    cudaGetSymbolAddress((void**)&v, g_v);

    static bool attr_set = false;
    if (!attr_set) {
        cudaFuncSetAttribute(av_mma_kernel, cudaFuncAttributeMaxDynamicSharedMemorySize, AV_SMEM_BYTES);
        attr_set = true;
    }

    const int M = BATCH * SEQ;  // 65536

    // Projections (v stored tf32-rounded for the MMA consumer)
    proj_kernel<<<dim3(DIM / 64, M / 128), 256>>>(x, Wq, bq, q, DIM, 0);
    proj_kernel<<<dim3(DIM / 64, M / 128), 256>>>(x, Wk, bk, k, DIM, 0);
    proj_kernel<<<dim3(CH  / 64, M / 128), 256>>>(x, Wv, bv, v, CH, 1);

    // Logits straight into attention output region
    energy_kernel<<<dim3(SEQ / 128, SEQ / 128, BATCH), 256>>>(q, k, att);

    // In-place row softmax (stores tf32-rounded probs)
    softmax_kernel<<<M, 256>>>(att);

    // attn @ V on legacy tensor cores (tf32 mma.sync), fused gamma-residual
    av_mma_kernel<<<dim3(CH / 128, SEQ / 128, BATCH), 256, AV_SMEM_BYTES>>>(att, v, x, gamma, out);
}

// round 10
// speedup vs baseline: 2.1763x; 1.0772x over previous
#include <cuda_runtime.h>
#include <cstdint>

#define BATCH 16
#define SEQ   4096
#define CH    512
#define DIM   64

// Scratch (allocation-free per harness rules)
__device__ float g_q[BATCH * SEQ * DIM];
__device__ float g_k[BATCH * SEQ * DIM];
__device__ float g_v[BATCH * SEQ * CH];

// ===========================================================================
// helpers
// ===========================================================================
__device__ __forceinline__ uint32_t smem_u32(const void* p) {
    uint32_t a;
    asm("{ .reg .u64 t; cvta.to.shared.u64 t, %1; cvt.u32.u64 %0, t; }" : "=r"(a) : "l"(p));
    return a;
}
__device__ __forceinline__ float tf32r(float x) {
    uint32_t r;
    asm("cvt.rna.tf32.f32 %0, %1;" : "=r"(r) : "f"(x));
    return __uint_as_float(r);
}
__device__ __forceinline__ void cp16(uint32_t dst, const void* src) {
    asm volatile("cp.async.cg.shared.global [%0], [%1], 16;" :: "r"(dst), "l"(src));
}
#define CP_COMMIT() asm volatile("cp.async.commit_group;" ::: "memory")
#define CP_WAIT_1() asm volatile("cp.async.wait_group 1;" ::: "memory")
#define CP_WAIT_0() asm volatile("cp.async.wait_group 0;" ::: "memory")

#define MMA_TF32(c, a0, a1, a2, a3, b0, b1) \
    asm volatile( \
        "mma.sync.aligned.m16n8k8.row.col.f32.tf32.tf32.f32 " \
        "{%0,%1,%2,%3}, {%4,%5,%6,%7}, {%8,%9}, {%0,%1,%2,%3};" \
        : "+f"((c)[0]), "+f"((c)[1]), "+f"((c)[2]), "+f"((c)[3]) \
        : "r"(a0), "r"(a1), "r"(a2), "r"(a3), "r"(b0), "r"(b1))

// ===========================================================================
// proj: C[M,N] = A[M,512] @ W[512,N] + bias.  round_out: store tf32-rounded.
// ===========================================================================
__global__ __launch_bounds__(256, 2)
void proj_kernel(const float* __restrict__ A, const float* __restrict__ W,
                 const float* __restrict__ bias, float* __restrict__ C, int N,
                 int round_out) {
    const int K = CH;
    __shared__ float As[32][132];
    __shared__ float Ws[32][64];
    const int bm = blockIdx.y * 128;
    const int bn = blockIdx.x * 64;
    const int tid = threadIdx.x;
    const int tn = tid & 15;
    const int tm = tid >> 4;
    float acc[8][4] = {};

    for (int k0 = 0; k0 < K; k0 += 32) {
        #pragma unroll
        for (int i = 0; i < 4; i++) {
            int fidx = tid + i * 256;
            int row  = fidx >> 3;
            int kc   = (fidx & 7) * 4;
            float4 t = *(const float4*)(A + (size_t)(bm + row) * K + k0 + kc);
            As[kc + 0][row] = t.x; As[kc + 1][row] = t.y;
            As[kc + 2][row] = t.z; As[kc + 3][row] = t.w;
        }
        #pragma unroll
        for (int i = 0; i < 2; i++) {
            int fidx = tid + i * 256;
            int kr   = fidx >> 4;
            int nc   = (fidx & 15) * 4;
            *(float4*)&Ws[kr][nc] = *(const float4*)(W + (size_t)(k0 + kr) * N + bn + nc);
        }
        __syncthreads();
        #pragma unroll
        for (int kk = 0; kk < 32; kk++) {
            float4 a0 = *(const float4*)&As[kk][tm * 8];
            float4 a1 = *(const float4*)&As[kk][tm * 8 + 4];
            float4 w0 = *(const float4*)&Ws[kk][tn * 4];
            float a[8] = {a0.x, a0.y, a0.z, a0.w, a1.x, a1.y, a1.z, a1.w};
            float w[4] = {w0.x, w0.y, w0.z, w0.w};
            #pragma unroll
            for (int i = 0; i < 8; i++)
                #pragma unroll
                for (int j = 0; j < 4; j++)
                    acc[i][j] = fmaf(a[i], w[j], acc[i][j]);
        }
        __syncthreads();
    }
    #pragma unroll
    for (int i = 0; i < 8; i++) {
        size_t row = bm + tm * 8 + i;
        int col = bn + tn * 4;
        float4 o;
        o.x = acc[i][0] + bias[col + 0];
        o.y = acc[i][1] + bias[col + 1];
        o.z = acc[i][2] + bias[col + 2];
        o.w = acc[i][3] + bias[col + 3];
        if (round_out) {
            o.x = tf32r(o.x); o.y = tf32r(o.y);
            o.z = tf32r(o.z); o.w = tf32r(o.w);
        }
        *(float4*)(C + row * N + col) = o;
    }
}

// ===========================================================================
// energy_mma: E[b,m,n] = sum_d Q[b,m,d] * K[b,n,d] on tensor cores.
// Dekker hi/lo tf32 split (3 MMAs) -> fp32-accurate logits.
// Tile 128m x 64n, K=64 (whole reduction, single load).
// 8 warps of 64x16 (mt=4, nt=2).
// ===========================================================================
#define EA_STRIDE 68
#define EK_STRIDE 72
#define E_SMEM_BYTES ((128 * EA_STRIDE + 64 * EK_STRIDE) * 4)   // 53248

__global__ __launch_bounds__(256, 2)
void energy_mma_kernel(const float* __restrict__ Q, const float* __restrict__ Kd,
                       float* __restrict__ E) {
    extern __shared__ float smemf[];
    float* As = smemf;                       // [128][68]  A[m][k]
    float* Ks = smemf + 128 * EA_STRIDE;     // [64][72]   B[k][n] (transposed keys)
    uint32_t sb = smem_u32(smemf);

    const int tid  = threadIdx.x;
    const int wid  = tid >> 5;
    const int lane = tid & 31;
    const int gid  = lane >> 2;      // 0..7
    const int tig  = lane & 3;       // 0..3
    const int wm   = (wid >> 2) * 64;    // 0 or 64
    const int wn   = (wid & 3) * 16;     // 0,16,32,48

    const int bz = blockIdx.z;
    const int bm = blockIdx.y * 128;
    const int bn = blockIdx.x * 64;
    const float* Qb = Q  + ((size_t)bz * SEQ + bm) * DIM;
    const float* Kb = Kd + ((size_t)bz * SEQ + bn) * DIM;
    float* Eb = E + (size_t)bz * SEQ * SEQ;

    // Load A tile (128x64) via cp.async, row-major, stride 68
    #pragma unroll
    for (int j = 0; j < 8; j++) {
        int idx = tid + j * 256;     // 0..2047
        int r   = idx >> 4;          // 0..127
        int c   = idx & 15;          // 16B chunk
        cp16(sb + (r * EA_STRIDE + c * 4) * 4, Qb + (size_t)r * DIM + c * 4);
    }
    CP_COMMIT();

    // Load K tile (64 keys x 64 dims) transposed into Ks[d][n], stride 72
    #pragma unroll
    for (int j = 0; j < 4; j++) {
        int idx = tid + j * 256;     // 0..1023
        int row = idx >> 4;          // key 0..63
        int kc  = (idx & 15) * 4;    // dim 0..60
        float4 u = *(const float4*)(Kb + (size_t)row * DIM + kc);
        Ks[(kc + 0) * EK_STRIDE + row] = u.x;
        Ks[(kc + 1) * EK_STRIDE + row] = u.y;
        Ks[(kc + 2) * EK_STRIDE + row] = u.z;
        Ks[(kc + 3) * EK_STRIDE + row] = u.w;
    }
    CP_WAIT_0();
    __syncthreads();

    float acc[8][4];
    #pragma unroll
    for (int i = 0; i < 8; i++)
        #pragma unroll
        for (int j = 0; j < 4; j++) acc[i][j] = 0.f;

    #pragma unroll
    for (int kk = 0; kk < 64; kk += 8) {
        uint32_t ah[4][4], al[4][4], bh[2][2], bl[2][2];
        #pragma unroll
        for (int mt = 0; mt < 4; mt++) {
            int r = wm + mt * 16 + gid;
            float v0 = As[r * EA_STRIDE + kk + tig];
            float v1 = As[(r + 8) * EA_STRIDE + kk + tig];
            float v2 = As[r * EA_STRIDE + kk + tig + 4];
            float v3 = As[(r + 8) * EA_STRIDE + kk + tig + 4];
            float h0 = tf32r(v0), h1 = tf32r(v1), h2 = tf32r(v2), h3 = tf32r(v3);
            ah[mt][0] = __float_as_uint(h0); al[mt][0] = __float_as_uint(tf32r(v0 - h0));
            ah[mt][1] = __float_as_uint(h1); al[mt][1] = __float_as_uint(tf32r(v1 - h1));
            ah[mt][2] = __float_as_uint(h2); al[mt][2] = __float_as_uint(tf32r(v2 - h2));
            ah[mt][3] = __float_as_uint(h3); al[mt][3] = __float_as_uint(tf32r(v3 - h3));
        }
        #pragma unroll
        for (int nt = 0; nt < 2; nt++) {
            int n = wn + nt * 8 + gid;
            float v0 = Ks[(kk + tig) * EK_STRIDE + n];
            float v1 = Ks[(kk + tig + 4) * EK_STRIDE + n];
            float h0 = tf32r(v0), h1 = tf32r(v1);
            bh[nt][0] = __float_as_uint(h0); bl[nt][0] = __float_as_uint(tf32r(v0 - h0));
            bh[nt][1] = __float_as_uint(h1); bl[nt][1] = __float_as_uint(tf32r(v1 - h1));
        }
        #pragma unroll
        for (int mt = 0; mt < 4; mt++)
            #pragma unroll
            for (int nt = 0; nt < 2; nt++) {
                float* c = acc[mt * 2 + nt];
                MMA_TF32(c, ah[mt][0], ah[mt][1], ah[mt][2], ah[mt][3], bh[nt][0], bh[nt][1]);
                MMA_TF32(c, ah[mt][0], ah[mt][1], ah[mt][2], ah[mt][3], bl[nt][0], bl[nt][1]);
                MMA_TF32(c, al[mt][0], al[mt][1], al[mt][2], al[mt][3], bh[nt][0], bh[nt][1]);
            }
    }

    // write logits
    #pragma unroll
    for (int mt = 0; mt < 4; mt++) {
        int r0 = bm + wm + mt * 16 + gid;
        size_t base0 = (size_t)r0 * SEQ;
        size_t base1 = base0 + 8 * SEQ;
        #pragma unroll
        for (int nt = 0; nt < 2; nt++) {
            float* c = acc[mt * 2 + nt];
            int col = bn + wn + nt * 8 + 2 * tig;
            *(float2*)(Eb + base0 + col) = make_float2(c[0], c[1]);
            *(float2*)(Eb + base1 + col) = make_float2(c[2], c[3]);
        }
    }
}

// ===========================================================================
// softmax: in-place row softmax; final probs stored tf32-rounded.
// ===========================================================================
__global__ __launch_bounds__(256)
void softmax_kernel(float* __restrict__ E) {
    const int tid = threadIdx.x;
    float4* p = (float4*)(E + (size_t)blockIdx.x * SEQ);
    float4 v[4];
    float mx = -3.4e38f;
    #pragma unroll
    for (int i = 0; i < 4; i++) {
        v[i] = p[tid + i * 256];
        mx = fmaxf(mx, fmaxf(fmaxf(v[i].x, v[i].y), fmaxf(v[i].z, v[i].w)));
    }
    __shared__ float sred[8];
    #pragma unroll
    for (int o = 16; o > 0; o >>= 1) mx = fmaxf(mx, __shfl_xor_sync(0xffffffffu, mx, o));
    if ((tid & 31) == 0) sred[tid >> 5] = mx;
    __syncthreads();
    if (tid == 0) {
        float m = sred[0];
        #pragma unroll
        for (int i = 1; i < 8; i++) m = fmaxf(m, sred[i]);
        sred[0] = m;
    }
    __syncthreads();
    mx = sred[0];
    __syncthreads();

    float s = 0.f;
    #pragma unroll
    for (int i = 0; i < 4; i++) {
        v[i].x = __expf(v[i].x - mx);
        v[i].y = __expf(v[i].y - mx);
        v[i].z = __expf(v[i].z - mx);
        v[i].w = __expf(v[i].w - mx);
        s += (v[i].x + v[i].y) + (v[i].z + v[i].w);
    }
    #pragma unroll
    for (int o = 16; o > 0; o >>= 1) s += __shfl_xor_sync(0xffffffffu, s, o);
    if ((tid & 31) == 0) sred[tid >> 5] = s;
    __syncthreads();
    if (tid == 0) {
        float t = 0.f;
        #pragma unroll
        for (int i = 0; i < 8; i++) t += sred[i];
        sred[0] = t;
    }
    __syncthreads();
    float inv = 1.0f / sred[0];
    #pragma unroll
    for (int i = 0; i < 4; i++) {
        v[i].x = tf32r(v[i].x * inv);
        v[i].y = tf32r(v[i].y * inv);
        v[i].z = tf32r(v[i].z * inv);
        v[i].w = tf32r(v[i].w * inv);
        p[tid + i * 256] = v[i];
    }
}

// ===========================================================================
// av_mma: Out[b,m,c] = gamma * (Att @ V)[b,m,c] + X[b,m,c]
// mma.sync m16n8k8 tf32. Block 128x128xK32, 8 warps of 64x32, 2-stage
// cp.async double buffer.
// ===========================================================================
#define A_STRIDE 36
#define B_STRIDE 136
#define A_STAGE_F (128 * A_STRIDE)
#define B_STAGE_F (32 * B_STRIDE)
#define AV_SMEM_F (2 * A_STAGE_F + 2 * B_STAGE_F)
#define AV_SMEM_BYTES (AV_SMEM_F * 4)

__device__ __forceinline__ void av_load_stage(uint32_t sb, const float* __restrict__ Ab,
                                              const float* __restrict__ Vb,
                                              int k0, int buf, int tid, int bn) {
    uint32_t abase = sb + buf * (A_STAGE_F * 4);
    #pragma unroll
    for (int j = 0; j < 4; j++) {
        int idx = tid + j * 256;
        int r   = idx >> 3;
        int c   = idx & 7;
        cp16(abase + (r * A_STRIDE + c * 4) * 4, Ab + (size_t)r * SEQ + k0 + c * 4);
    }
    uint32_t bbase = sb + (2 * A_STAGE_F + buf * B_STAGE_F) * 4;
    #pragma unroll
    for (int j = 0; j < 4; j++) {
        int idx = tid + j * 256;
        int kr  = idx >> 5;
        int c   = idx & 31;
        cp16(bbase + (kr * B_STRIDE + c * 4) * 4, Vb + (size_t)(k0 + kr) * CH + bn + c * 4);
    }
}

__global__ __launch_bounds__(256, 2)
void av_mma_kernel(const float* __restrict__ Att, const float* __restrict__ V,
                   const float* __restrict__ X, const float* __restrict__ gamma,
                   float* __restrict__ Out) {
    extern __shared__ float smemf[];
    uint32_t sb = smem_u32(smemf);
    const int tid  = threadIdx.x;
    const int wid  = tid >> 5;
    const int lane = tid & 31;
    const int gid  = lane >> 2;
    const int tig  = lane & 3;
    const int wm   = (wid >> 2) * 64;
    const int wn   = (wid & 3) * 32;

    const int bz = blockIdx.z;
    const int bm = blockIdx.y * 128;
    const int bn = blockIdx.x * 128;
    const float* Ab = Att + ((size_t)bz * SEQ + bm) * SEQ;
    const float* Vb = V   + (size_t)bz * SEQ * CH;

    float acc[16][4];
    #pragma unroll
    for (int i = 0; i < 16; i++)
        #pragma unroll
        for (int j = 0; j < 4; j++) acc[i][j] = 0.f;

    av_load_stage(sb, Ab, Vb, 0,  0, tid, bn); CP_COMMIT();
    av_load_stage(sb, Ab, Vb, 32, 1, tid, bn); CP_COMMIT();

    const int NS = SEQ / 32;
    for (int s = 0; s < NS; s++) {
        const int buf = s & 1;
        if (s < NS - 1) { CP_WAIT_1(); } else { CP_WAIT_0(); }
        __syncthreads();

        const float* As = smemf + buf * A_STAGE_F;
        const float* Bs = smemf + 2 * A_STAGE_F + buf * B_STAGE_F;

        #pragma unroll
        for (int kk = 0; kk < 32; kk += 8) {
            uint32_t a[4][4], b[4][2];
            #pragma unroll
            for (int mt = 0; mt < 4; mt++) {
                int r = wm + mt * 16 + gid;
                a[mt][0] = __float_as_uint(As[r * A_STRIDE + kk + tig]);
                a[mt][1] = __float_as_uint(As[(r + 8) * A_STRIDE + kk + tig]);
                a[mt][2] = __float_as_uint(As[r * A_STRIDE + kk + tig + 4]);
                a[mt][3] = __float_as_uint(As[(r + 8) * A_STRIDE + kk + tig + 4]);
            }
            #pragma unroll
            for (int nt = 0; nt < 4; nt++) {
                int n = wn + nt * 8 + gid;
                b[nt][0] = __float_as_uint(Bs[(kk + tig) * B_STRIDE + n]);
                b[nt][1] = __float_as_uint(Bs[(kk + tig + 4) * B_STRIDE + n]);
            }
            #pragma unroll
            for (int mt = 0; mt < 4; mt++)
                #pragma unroll
                for (int nt = 0; nt < 4; nt++)
                    MMA_TF32(acc[mt * 4 + nt], a[mt][0], a[mt][1], a[mt][2], a[mt][3],
                             b[nt][0], b[nt][1]);
        }
        __syncthreads();
        if (s + 2 < NS) {
            av_load_stage(sb, Ab, Vb, (s + 2) * 32, buf, tid, bn);
            CP_COMMIT();
        }
    }

    const float g = gamma[0];
    #pragma unroll
    for (int mt = 0; mt < 4; mt++) {
        int r0 = bm + wm + mt * 16 + gid;
        size_t base0 = ((size_t)bz * SEQ + r0) * CH;
        size_t base1 = base0 + 8 * CH;
        #pragma unroll
        for (int nt = 0; nt < 4; nt++) {
            float* c = acc[mt * 4 + nt];
            int col = bn + wn + nt * 8 + 2 * tig;
            float2 x0 = *(const float2*)(X + base0 + col);
            float2 x1 = *(const float2*)(X + base1 + col);
            float2 o0, o1;
            o0.x = fmaf(g, c[0], x0.x); o0.y = fmaf(g, c[1], x0.y);
            o1.x = fmaf(g, c[2], x1.x); o1.y = fmaf(g, c[3], x1.y);
            *(float2*)(Out + base0 + col) = o0;
            *(float2*)(Out + base1 + col) = o1;
        }
    }
}

// ===========================================================================
extern "C" void kernel_launch(void* const* d_in, const int* in_sizes, int n_in,
                              void* d_out, int out_size) {
    const float* x     = (const float*)d_in[0];
    const float* Wq    = (const float*)d_in[1];
    const float* bq    = (const float*)d_in[2];
    const float* Wk    = (const float*)d_in[3];
    const float* bk    = (const float*)d_in[4];
    const float* Wv    = (const float*)d_in[5];
    const float* bv    = (const float*)d_in[6];
    const float* gamma = (const float*)d_in[7];

    float* out = (float*)d_out;                              // [B, N, C]
    float* att = out + (size_t)BATCH * SEQ * CH;             // [B, N, N]

    float *q, *k, *v;
    cudaGetSymbolAddress((void**)&q, g_q);
    cudaGetSymbolAddress((void**)&k, g_k);
    cudaGetSymbolAddress((void**)&v, g_v);

    static bool attr_set = false;
    if (!attr_set) {
        cudaFuncSetAttribute(av_mma_kernel, cudaFuncAttributeMaxDynamicSharedMemorySize, AV_SMEM_BYTES);
        cudaFuncSetAttribute(energy_mma_kernel, cudaFuncAttributeMaxDynamicSharedMemorySize, E_SMEM_BYTES);
        attr_set = true;
    }

    const int M = BATCH * SEQ;  // 65536

    // Projections (v stored tf32-rounded for the MMA consumer)
    proj_kernel<<<dim3(DIM / 64, M / 128), 256>>>(x, Wq, bq, q, DIM, 0);
    proj_kernel<<<dim3(DIM / 64, M / 128), 256>>>(x, Wk, bk, k, DIM, 0);
    proj_kernel<<<dim3(CH  / 64, M / 128), 256>>>(x, Wv, bv, v, CH, 1);

    // Logits on tensor cores (Dekker tf32 split -> fp32-accurate)
    energy_mma_kernel<<<dim3(SEQ / 64, SEQ / 128, BATCH), 256, E_SMEM_BYTES>>>(q, k, att);

    // In-place row softmax (stores tf32-rounded probs)
    softmax_kernel<<<M, 256>>>(att);

    // attn @ V on tensor cores (tf32 mma.sync), fused gamma-residual
    av_mma_kernel<<<dim3(CH / 128, SEQ / 128, BATCH), 256, AV_SMEM_BYTES>>>(att, v, x, gamma, out);
}